// round 13
// baseline (speedup 1.0000x reference)
#include <cuda_runtime.h>
#include <cstdint>

// S4D Vandermonde kernel:  K[h,l] = 2 * sum_n C_eff[h,n] * exp(dtA[h,n] * l)
// H=256, NH=N/2=32, L=16384.
//
// With this problem's init dtA[h,n] is constant across n, so
// K[h,l] = S[h] * exp(dtA[h]*l): one geometric recurrence per head.
// R12 = R8 hot path (best measured) + prologue amortization: each warp owns
// REP=2 chunks of the SAME head via a strided loop, so the expensive
// LDG -> coefficient -> ballot -> shfl-reduce prologue runs once per 2 tiles
// (prologue count and front-batched LDG queue pressure both halve; the
// second tile reseeds with one independent MUFU). No extra kernels, no
// barriers, no store-path changes -- those all regressed in R4/R7/R9/R10.

#define TPB    256
#define NH     32
#define WPB    (TPB / 32)      // warps per block
#define JF     4               // float4 stores per lane per tile
#define WCHUNK (32 * 4 * JF)   // 512 l-elements per tile
#define REP    2               // tiles per warp (same head)
#define LOG2E  1.4426950408889634f

typedef unsigned long long ull;

__device__ __forceinline__ float ex2(float x) {
    float y; asm("ex2.approx.f32 %0, %1;" : "=f"(y) : "f"(x));
    return y;
}
__device__ __forceinline__ ull mul2(ull a, ull b) {
    ull d; asm("mul.rn.f32x2 %0, %1, %2;" : "=l"(d) : "l"(a), "l"(b));
    return d;
}
__device__ __forceinline__ ull pack2(float lo, float hi) {
    ull u; asm("mov.b64 %0, {%1, %2};" : "=l"(u) : "f"(lo), "f"(hi));
    return u;
}
__device__ __forceinline__ void unpack2(ull u, float& lo, float& hi) {
    asm("mov.b64 {%0, %1}, %2;" : "=f"(lo), "=f"(hi) : "l"(u));
}

__global__ void __launch_bounds__(TPB, 8) s4d_kernel(
    const float* __restrict__ log_dt,      // [H]
    const float* __restrict__ C,           // [H, NH]
    const float* __restrict__ log_A_real,  // [H, NH]
    const float* __restrict__ A_imag,      // [H, NH]
    float* __restrict__ out,               // [H, L]
    int L)
{
    const int h      = blockIdx.y;
    const int lane   = threadIdx.x & 31;
    const int wslot  = blockIdx.x * WPB + (threadIdx.x >> 5);   // warp slot
    const int nslots = gridDim.x * WPB;                         // warps per head
    const int cb0    = wslot * WCHUNK;
    if (cb0 >= L) return;
    const int cstride = nslots * WCHUNK;   // l-distance between a warp's tiles

    // ---- per-warp prologue (ONCE per REP tiles): lane == n. Mirrors
    // reference fp32 math with MUFU-grade exp/div (rel err ~2^-21 vs 1e-3).
    float dt     = ex2(log_dt[h] * LOG2E);
    float Ar     = -ex2(log_A_real[h * NH + lane] * LOG2E);
    float Ai     = A_imag[h * NH + lane];
    float dtA    = Ar * dt;
    float den    = Ar * Ar + Ai * Ai;
    float expdtA = ex2(dtA * LOG2E);
    float c      = __fdividef(2.0f * C[h * NH + lane] * (expdtA - 1.0f) * Ar, den);

    const float dtA0  = __shfl_sync(0xffffffffu, dtA, 0);
    const unsigned eq = __ballot_sync(0xffffffffu,
                          __float_as_uint(dtA) == __float_as_uint(dtA0));
    float S = c;
#pragma unroll
    for (int o = 16; o; o >>= 1)
        S += __shfl_xor_sync(0xffffffffu, S, o);

    float* orow = out + (size_t)h * L;

    if (eq == 0xffffffffu) {
        // ---- hot path: K = S * exp(dtA0 * l); S folded into each seed ----
        const float E   = dtA0 * LOG2E;
        const float q1  = expdtA;               // exp(dtA0) on this path
        const float stp = ex2(E * 128.0f);      // j-step ratio (32 lanes * 4)
        const ull   st2 = pack2(stp, stp);

        for (int cb = cb0; cb < L; cb += cstride) {
            // reseed per tile: one independent MUFU
            float p0 = S * ex2(E * (float)(cb + 4 * lane));
            float p1 = p0 * q1;
            float p2 = p1 * q1;
            float p3 = p2 * q1;
            ull pa = pack2(p0, p1);
            ull pb = pack2(p2, p3);

            float4* o = (float4*)(orow + cb) + lane;
            if (cb + WCHUNK <= L) {
#pragma unroll
                for (int j = 0; j < JF; j++) {
                    float4 v;
                    unpack2(pa, v.x, v.y);
                    unpack2(pb, v.z, v.w);
                    o[j * 32] = v;               // unconditional STG.128
                    pa = mul2(pa, st2);
                    pb = mul2(pb, st2);
                }
            } else {
                const int lrem = cb + 4 * lane;
#pragma unroll
                for (int j = 0; j < JF; j++) {
                    float4 v;
                    unpack2(pa, v.x, v.y);
                    unpack2(pb, v.z, v.w);
                    if (lrem + j * 128 + 3 < L) o[j * 32] = v;
                    pa = mul2(pa, st2);
                    pb = mul2(pb, st2);
                }
            }
        }
    } else {
        // ---- cold path: direct evaluation via shfl-gathered coefficients ----
        for (int cb = cb0; cb < L; cb += cstride) {
            for (int k = 0; k < WCHUNK / 32; k++) {
                const int l = cb + lane + k * 32;
                float lf = (float)l;
                float acc = 0.0f;
#pragma unroll 4
                for (int i = 0; i < NH; i++) {
                    float ci = __shfl_sync(0xffffffffu, c,   i);
                    float di = __shfl_sync(0xffffffffu, dtA, i);
                    acc += ci * ex2(di * LOG2E * lf);
                }
                if (l < L) orow[l] = acc;
            }
        }
    }
}

extern "C" void kernel_launch(void* const* d_in, const int* in_sizes, int n_in,
                              void* d_out, int out_size)
{
    const float* log_dt     = (const float*)d_in[0];
    const float* C          = (const float*)d_in[1];
    const float* log_A_real = (const float*)d_in[2];
    const float* A_imag     = (const float*)d_in[3];
    float* out = (float*)d_out;

    const int H = in_sizes[0];
    const int L = out_size / H;

    const int chunks = (L + WCHUNK - 1) / WCHUNK;          // tiles per head
    const int slots  = (chunks + REP - 1) / REP;           // warps per head
    dim3 grid((slots + WPB - 1) / WPB, H);
    s4d_kernel<<<grid, TPB>>>(log_dt, C, log_A_real, A_imag, out, L);
}

// round 14
// speedup vs baseline: 1.3077x; 1.3077x over previous
#include <cuda_runtime.h>
#include <cstdint>

// S4D Vandermonde kernel:  K[h,l] = 2 * sum_n C_eff[h,n] * exp(dtA[h,n] * l)
// H=256, NH=N/2=32, L=16384.
//
// With this problem's init dtA[h,n] is constant across n, so
// K[h,l] = S[h] * exp(dtA[h]*l): one geometric recurrence per head.
// R13 = R8 locked (best of 6 structural variants: per-warp autonomous
// prologue, JF=4, grid 1024, direct STG.128 — block-setup/barrier, extra
// kernels, smem+bulk stores, REP-amortization all measured neutral or worse)
// + seed-chain depth trim: q2 = q1^2 gives p2 = p0*q2, p3 = p1*q2, halving
// the dependent-FMUL depth between the seed MUFU and the first store.
// Floor analysis: remaining time = fixed launch ramp (~5000 cyc) + L2-capped
// store drain (16.8MB @ ~6300 B/cyc); both structure-independent.

#define TPB    256
#define NH     32
#define WPB    (TPB / 32)      // warps per block
#define JF     4               // float4 stores per lane
#define WCHUNK (32 * 4 * JF)   // 512 l-elements per warp
#define LOG2E  1.4426950408889634f

typedef unsigned long long ull;

__device__ __forceinline__ float ex2(float x) {
    float y; asm("ex2.approx.f32 %0, %1;" : "=f"(y) : "f"(x));
    return y;
}
__device__ __forceinline__ ull mul2(ull a, ull b) {
    ull d; asm("mul.rn.f32x2 %0, %1, %2;" : "=l"(d) : "l"(a), "l"(b));
    return d;
}
__device__ __forceinline__ ull pack2(float lo, float hi) {
    ull u; asm("mov.b64 %0, {%1, %2};" : "=l"(u) : "f"(lo), "f"(hi));
    return u;
}
__device__ __forceinline__ void unpack2(ull u, float& lo, float& hi) {
    asm("mov.b64 {%0, %1}, %2;" : "=f"(lo), "=f"(hi) : "l"(u));
}

__global__ void __launch_bounds__(TPB) s4d_kernel(
    const float* __restrict__ log_dt,      // [H]
    const float* __restrict__ C,           // [H, NH]
    const float* __restrict__ log_A_real,  // [H, NH]
    const float* __restrict__ A_imag,      // [H, NH]
    float* __restrict__ out,               // [H, L]
    int L)
{
    const int h     = blockIdx.y;
    const int lane  = threadIdx.x & 31;
    const int chunk = blockIdx.x * WPB + (threadIdx.x >> 5);
    const int cbase = chunk * WCHUNK;
    if (cbase >= L) return;

    // ---- per-warp setup: lane == n. Mirrors reference fp32 math with
    // MUFU-grade exp/div (rel err ~2^-21 vs the 1e-3 gate).
    float dt     = ex2(log_dt[h] * LOG2E);
    float Ar     = -ex2(log_A_real[h * NH + lane] * LOG2E);
    float Ai     = A_imag[h * NH + lane];
    float dtA    = Ar * dt;
    float den    = Ar * Ar + Ai * Ai;
    float expdtA = ex2(dtA * LOG2E);
    float c      = __fdividef(2.0f * C[h * NH + lane] * (expdtA - 1.0f) * Ar, den);

    const float dtA0  = __shfl_sync(0xffffffffu, dtA, 0);
    const unsigned eq = __ballot_sync(0xffffffffu,
                          __float_as_uint(dtA) == __float_as_uint(dtA0));
    float S = c;
#pragma unroll
    for (int o = 16; o; o >>= 1)
        S += __shfl_xor_sync(0xffffffffu, S, o);

    float* obase = out + (size_t)h * L + cbase;

    if (eq == 0xffffffffu) {
        // ---- hot path: K = S * exp(dtA0 * l); S folded into the seed.
        // Seed chain depth 2 after the MUFU: p1 = p0*q1; {p2,p3} = {p0,p1}*q2.
        const float E   = dtA0 * LOG2E;
        const float q1  = expdtA;               // exp(dtA0) on this path
        const float q2  = q1 * q1;
        const float stp = ex2(E * 128.0f);      // j-step ratio (32 lanes * 4)
        float p0 = S * ex2(E * (float)(cbase + 4 * lane));
        float p1 = p0 * q1;
        float p2 = p0 * q2;
        float p3 = p1 * q2;

        ull pa = pack2(p0, p1);
        ull pb = pack2(p2, p3);
        const ull st2 = pack2(stp, stp);

        float4* o = (float4*)(obase) + lane;
        if (cbase + WCHUNK <= L) {
#pragma unroll
            for (int j = 0; j < JF; j++) {
                float4 v;
                unpack2(pa, v.x, v.y);
                unpack2(pb, v.z, v.w);
                o[j * 32] = v;                   // unconditional STG.128
                pa = mul2(pa, st2);
                pb = mul2(pb, st2);
            }
        } else {
            const int lrem = cbase + 4 * lane;
#pragma unroll
            for (int j = 0; j < JF; j++) {
                float4 v;
                unpack2(pa, v.x, v.y);
                unpack2(pb, v.z, v.w);
                if (lrem + j * 128 + 3 < L) o[j * 32] = v;
                pa = mul2(pa, st2);
                pb = mul2(pb, st2);
            }
        }
    } else {
        // ---- cold path: direct evaluation via shfl-gathered coefficients ----
        for (int k = 0; k < WCHUNK / 32; k++) {
            const int l = cbase + lane + k * 32;
            float lf = (float)l;
            float acc = 0.0f;
#pragma unroll 4
            for (int i = 0; i < NH; i++) {
                float ci = __shfl_sync(0xffffffffu, c,   i);
                float di = __shfl_sync(0xffffffffu, dtA, i);
                acc += ci * ex2(di * LOG2E * lf);
            }
            if (l < L) obase[lane + k * 32] = acc;
        }
    }
}

extern "C" void kernel_launch(void* const* d_in, const int* in_sizes, int n_in,
                              void* d_out, int out_size)
{
    const float* log_dt     = (const float*)d_in[0];
    const float* C          = (const float*)d_in[1];
    const float* log_A_real = (const float*)d_in[2];
    const float* A_imag     = (const float*)d_in[3];
    float* out = (float*)d_out;

    const int H = in_sizes[0];
    const int L = out_size / H;

    const int chunks = (L + WCHUNK - 1) / WCHUNK;       // warps per head
    dim3 grid((chunks + WPB - 1) / WPB, H);
    s4d_kernel<<<grid, TPB>>>(log_dt, C, log_A_real, A_imag, out, L);
}